// round 9
// baseline (speedup 1.0000x reference)
#include <cuda_runtime.h>

// CompetingRiskTabMLoss: Cox PH partial likelihood (Breslow, K causes) + CE, blended.
// Inputs: log_h (N,M,K) f32, logits (N,M,5) f32, durations (N,) f32,
//         event_type (N,) i32, labels (N,) i32.  Output: scalar f32.
//
// Bucket-major pipeline: pass A scatters each sample directly into its duration
// bucket (fixed capacity + overflow list), bucket sums computed coalesced
// afterwards, 3-stage suffix scan, block-per-bucket event evaluation.

#define KC 4
#define NCLS 5
#define NB 8192              // duration buckets (durations ~ U[0,1))
#define CAPB 224             // slots per bucket (Poisson(122) + 9 sigma)
#define NPART 64             // scan partitions
#define BPP (NB / NPART)     // 128 buckets per partition
#define NMAX 1000000
#define EPS 1e-8
#define ALPHA 0.4

struct __align__(32) Elem {  // 32B = one sector
    float dur, f0, f1, f2, f3;
    float cause_bits;        // int cause as float bits
    float pad0, pad1;
};

// ---- scratch (no allocations allowed) ----
__device__ Elem   g_elem[(size_t)NB * CAPB];   // bucket-major samples
__device__ Elem   g_ovf[NMAX];                 // overflow list (normally empty)
__device__ int    g_ovfb[NMAX];                // overflow bucket ids
__device__ int    g_cnt[NB];
__device__ int    g_ovf_cnt;
__device__ double g_bsum[NB * KC];             // per-bucket sum exp(eta) per cause
__device__ double g_sufx[NB * KC];             // sum over buckets strictly greater
__device__ double g_part_sum[KC * NPART];
__device__ double g_part_sufx[KC * NPART];
__device__ double g_evsum[KC];
__device__ double g_evcnt[KC];
__device__ double g_ce;

// ---------------------------------------------------------------- helpers
__device__ __forceinline__ int bucket_of(float d) {
    int b = (int)(d * (float)NB);
    return b < 0 ? 0 : (b > NB - 1 ? NB - 1 : b);
}
__device__ __forceinline__ double warp_redd(double v) {
    #pragma unroll
    for (int o = 16; o; o >>= 1) v += __shfl_down_sync(0xffffffffu, v, o);
    return v;
}
__device__ __forceinline__ float elem_f(const float4& a, const float4& q, int c) {
    return (c == 0) ? a.y : (c == 1) ? a.z : (c == 2) ? a.w : q.x;
}

// ---------------------------------------------------------------- init
__global__ void k_init() {
    int i = blockIdx.x * blockDim.x + threadIdx.x;
    if (i < NB) g_cnt[i] = 0;
    if (i < KC) { g_evsum[i] = 0.0; g_evcnt[i] = 0.0; }
    if (i == 0) { g_ce = 0.0; g_ovf_cnt = 0; }
}

// ---------------------------------------------------------------- pass A (fused scatter)
__global__ void __launch_bounds__(256) k_passA(const float* __restrict__ log_h,
                        const float* __restrict__ logits,
                        const float* __restrict__ dur,
                        const int*   __restrict__ et,
                        const int*   __restrict__ labels,
                        int n, int M) {
    __shared__ double s_ce;
    if (threadIdx.x == 0) s_ce = 0.0;
    __syncthreads();

    int i = blockIdx.x * blockDim.x + threadIdx.x;
    double ce = 0.0;
    if (i < n) {
        // --- ensemble mean eta, clip, exp ---
        const float4* lh = reinterpret_cast<const float4*>(log_h) + (size_t)i * M;
        float4 s = make_float4(0.f, 0.f, 0.f, 0.f);
        #pragma unroll 8
        for (int m = 0; m < M; m++) {
            float4 v = lh[m];
            s.x += v.x; s.y += v.y; s.z += v.z; s.w += v.w;
        }
        float inv = 1.0f / (float)M;
        float ex0 = expf(fminf(fmaxf(s.x * inv, -50.f), 50.f));
        float ex1 = expf(fminf(fmaxf(s.y * inv, -50.f), 50.f));
        float ex2 = expf(fminf(fmaxf(s.z * inv, -50.f), 50.f));
        float ex3 = expf(fminf(fmaxf(s.w * inv, -50.f), 50.f));

        float d = dur[i];
        int cause = et[i];
        int b = bucket_of(d);
        int pos = atomicAdd(&g_cnt[b], 1);
        if (pos < CAPB) {
            float4* p = reinterpret_cast<float4*>(&g_elem[(size_t)b * CAPB + pos]);
            p[0] = make_float4(d, ex0, ex1, ex2);
            p[1] = make_float4(ex3, __int_as_float(cause), 0.f, 0.f);
        } else {
            int oi = atomicAdd(&g_ovf_cnt, 1);
            float4* p = reinterpret_cast<float4*>(&g_ovf[oi]);
            p[0] = make_float4(d, ex0, ex1, ex2);
            p[1] = make_float4(ex3, __int_as_float(cause), 0.f, 0.f);
            g_ovfb[oi] = b;
        }

        // --- CE on mean logits ---
        const float* lg = logits + (size_t)i * M * NCLS;
        float lm[NCLS];
        #pragma unroll
        for (int j = 0; j < NCLS; j++) lm[j] = 0.f;
        int total = M * NCLS;
        if ((total & 3) == 0) {
            const float4* lgv = reinterpret_cast<const float4*>(lg);
            for (int t = 0; t < total / 4; t++) {
                float4 v = lgv[t];
                int base = t * 4;
                lm[(base + 0) % NCLS] += v.x;
                lm[(base + 1) % NCLS] += v.y;
                lm[(base + 2) % NCLS] += v.z;
                lm[(base + 3) % NCLS] += v.w;
            }
        } else {
            for (int t = 0; t < total; t++) lm[t % NCLS] += lg[t];
        }
        float mj[NCLS], mx = -3.4e38f;
        #pragma unroll
        for (int j = 0; j < NCLS; j++) { mj[j] = lm[j] * inv; mx = fmaxf(mx, mj[j]); }
        float se = 0.f;
        #pragma unroll
        for (int j = 0; j < NCLS; j++) se += expf(mj[j] - mx);
        ce = (double)(mx + logf(se) - mj[labels[i]]);
    }
    double v = warp_redd(ce);
    if ((threadIdx.x & 31) == 0 && v != 0.0) atomicAdd(&s_ce, v);
    __syncthreads();
    if (threadIdx.x == 0 && s_ce != 0.0) atomicAdd(&g_ce, s_ce);
}

// ---------------------------------------------------------------- bucket sums (coalesced)
__global__ void __launch_bounds__(128) k_bsum() {
    __shared__ double sw[KC][4];
    int b = blockIdx.x, t = threadIdx.x;
    int w = t >> 5, lane = t & 31;
    int m = min(g_cnt[b], CAPB);
    double a0 = 0, a1 = 0, a2 = 0, a3 = 0;
    for (int j = t; j < m; j += 128) {
        const float4* p = reinterpret_cast<const float4*>(&g_elem[(size_t)b * CAPB + j]);
        float4 a = p[0], q = p[1];
        a0 += a.y; a1 += a.z; a2 += a.w; a3 += q.x;
    }
    a0 = warp_redd(a0); a1 = warp_redd(a1); a2 = warp_redd(a2); a3 = warp_redd(a3);
    if (lane == 0) { sw[0][w] = a0; sw[1][w] = a1; sw[2][w] = a2; sw[3][w] = a3; }
    __syncthreads();
    if (t < KC) g_bsum[b * KC + t] = sw[t][0] + sw[t][1] + sw[t][2] + sw[t][3];
}

// ---------------------------------------------------------------- overflow -> bucket sums
__global__ void __launch_bounds__(128) k_ovfadd() {
    int nov = g_ovf_cnt;
    for (int i = threadIdx.x; i < nov; i += 128) {
        const float4* p = reinterpret_cast<const float4*>(&g_ovf[i]);
        float4 a = p[0], q = p[1];
        int b = g_ovfb[i];
        atomicAdd(&g_bsum[b * KC + 0], (double)a.y);
        atomicAdd(&g_bsum[b * KC + 1], (double)a.z);
        atomicAdd(&g_bsum[b * KC + 2], (double)a.w);
        atomicAdd(&g_bsum[b * KC + 3], (double)q.x);
    }
}

// ---------------------------------------------------------------- suffix scan (3 stages)
__global__ void __launch_bounds__(BPP) k_sufA() {
    __shared__ double sd[BPP];
    int t = threadIdx.x, p = blockIdx.x;
    int b = p * BPP + t;
    for (int c = 0; c < KC; c++) {
        sd[t] = g_bsum[b * KC + c];
        __syncthreads();
        for (int off = BPP / 2; off; off >>= 1) {
            if (t < off) sd[t] += sd[t + off];
            __syncthreads();
        }
        if (t == 0) g_part_sum[c * NPART + p] = sd[0];
        __syncthreads();
    }
}

__global__ void __launch_bounds__(NPART) k_sufB() {
    __shared__ double sd[NPART];
    int t = threadIdx.x;
    for (int c = 0; c < KC; c++) {
        double own = g_part_sum[c * NPART + t];
        sd[t] = own;
        __syncthreads();
        for (int off = 1; off < NPART; off <<= 1) {
            double v = (t + off < NPART) ? sd[t + off] : 0.0;
            __syncthreads();
            sd[t] += v;
            __syncthreads();
        }
        g_part_sufx[c * NPART + t] = sd[t] - own;  // exclusive suffix over parts
        __syncthreads();
    }
}

__global__ void __launch_bounds__(BPP) k_sufC() {
    __shared__ double sd[BPP];
    int t = threadIdx.x, p = blockIdx.x;
    int b = p * BPP + t;
    for (int c = 0; c < KC; c++) {
        double own = g_bsum[b * KC + c];
        sd[t] = own;
        __syncthreads();
        for (int off = 1; off < BPP; off <<= 1) {
            double v = (t + off < BPP) ? sd[t + off] : 0.0;
            __syncthreads();
            sd[t] += v;
            __syncthreads();
        }
        g_sufx[b * KC + c] = g_part_sufx[c * NPART + p] + sd[t] - own;
        __syncthreads();
    }
}

// ---------------------------------------------------------------- events: block-per-bucket
__global__ void __launch_bounds__(128) k_events() {
    __shared__ float  sh_dur[CAPB];
    __shared__ float  sh_f[KC][CAPB];
    __shared__ int    sh_c[CAPB];
    __shared__ double s_sum[KC];
    __shared__ double s_cnt[KC];

    int b = blockIdx.x, t = threadIdx.x;
    if (t < KC) { s_sum[t] = 0.0; s_cnt[t] = 0.0; }

    int cnt = g_cnt[b];
    int m = min(cnt, CAPB);
    if (m == 0) return;

    for (int j = t; j < m; j += 128) {
        const float4* p = reinterpret_cast<const float4*>(&g_elem[(size_t)b * CAPB + j]);
        float4 a = p[0], q = p[1];
        sh_dur[j]  = a.x;
        sh_f[0][j] = a.y;
        sh_f[1][j] = a.z;
        sh_f[2][j] = a.w;
        sh_f[3][j] = q.x;
        sh_c[j]    = __float_as_int(q.y);
    }
    __syncthreads();

    int nov = (cnt > CAPB) ? g_ovf_cnt : 0;  // overflow only possible for this bucket if it spilled

    for (int j = t; j < m; j += 128) {
        int cv = sh_c[j];
        if (cv > 0) {
            int cc = cv - 1;
            float d_e = sh_dur[j];
            float fown = sh_f[cc][j];
            const float* fp = sh_f[cc];
            float acc = 0.f;
            for (int j2 = 0; j2 < m; j2++)
                acc += (sh_dur[j2] >= d_e) ? fp[j2] : 0.f;
            for (int j2 = 0; j2 < nov; j2++) {  // same-bucket overflow elems
                if (g_ovfb[j2] == b) {
                    const float4* p = reinterpret_cast<const float4*>(&g_ovf[j2]);
                    float4 a = p[0], q = p[1];
                    acc += (a.x >= d_e) ? elem_f(a, q, cc) : 0.f;
                }
            }
            double denom = g_sufx[b * KC + cc] + (double)acc;
            atomicAdd(&s_sum[cc], (double)logf(fown) - log(denom + EPS));
            atomicAdd(&s_cnt[cc], 1.0);
        }
    }
    __syncthreads();
    if (t < KC && s_cnt[t] != 0.0) {
        atomicAdd(&g_evsum[t], s_sum[t]);
        atomicAdd(&g_evcnt[t], s_cnt[t]);
    }
}

// ---------------------------------------------------------------- finalize (+ overflow events)
__global__ void k_fin(float* __restrict__ out, int n) {
    double esum[KC], ecnt[KC];
    #pragma unroll
    for (int c = 0; c < KC; c++) { esum[c] = g_evsum[c]; ecnt[c] = g_evcnt[c]; }

    int nov = g_ovf_cnt;  // normally 0
    for (int i = 0; i < nov; i++) {
        const float4* p = reinterpret_cast<const float4*>(&g_ovf[i]);
        float4 a = p[0], q = p[1];
        int cv = __float_as_int(q.y);
        if (cv <= 0) continue;
        int cc = cv - 1, b = g_ovfb[i];
        float d_e = a.x;
        float acc = 0.f;
        int m = min(g_cnt[b], CAPB);
        for (int j = 0; j < m; j++) {
            const float4* pj = reinterpret_cast<const float4*>(&g_elem[(size_t)b * CAPB + j]);
            float4 aj = pj[0], qj = pj[1];
            acc += (aj.x >= d_e) ? elem_f(aj, qj, cc) : 0.f;
        }
        for (int j = 0; j < nov; j++) {
            if (g_ovfb[j] == b) {
                const float4* pj = reinterpret_cast<const float4*>(&g_ovf[j]);
                float4 aj = pj[0], qj = pj[1];
                acc += (aj.x >= d_e) ? elem_f(aj, qj, cc) : 0.f;
            }
        }
        double denom = g_sufx[b * KC + cc] + (double)acc;
        esum[cc] += (double)logf(elem_f(a, q, cc)) - log(denom + EPS);
        ecnt[cc] += 1.0;
    }

    double ls = 0.0;
    #pragma unroll
    for (int c = 0; c < KC; c++) ls += -esum[c] / (ecnt[c] + EPS);
    double lc = g_ce / (double)n;
    out[0] = (float)(ALPHA * ls + (1.0 - ALPHA) * lc);
}

// ---------------------------------------------------------------- launch
extern "C" void kernel_launch(void* const* d_in, const int* in_sizes, int n_in,
                              void* d_out, int out_size) {
    const float* log_h  = (const float*)d_in[0];
    const float* logits = (const float*)d_in[1];
    const float* dur    = (const float*)d_in[2];
    const int*   et     = (const int*)d_in[3];
    const int*   labels = (const int*)d_in[4];
    float* out = (float*)d_out;

    int n = in_sizes[2];
    int M = in_sizes[0] / (n * KC);

    int tpb = 256;
    int nb  = (n + tpb - 1) / tpb;

    k_init<<<(NB + tpb - 1) / tpb, tpb>>>();
    k_passA<<<nb, tpb>>>(log_h, logits, dur, et, labels, n, M);
    k_bsum<<<NB, 128>>>();
    k_ovfadd<<<1, 128>>>();
    k_sufA<<<NPART, BPP>>>();
    k_sufB<<<1, NPART>>>();
    k_sufC<<<NPART, BPP>>>();
    k_events<<<NB, 128>>>();
    k_fin<<<1, 1>>>(out, n);
}

// round 10
// speedup vs baseline: 1.0700x; 1.0700x over previous
#include <cuda_runtime.h>

// CompetingRiskTabMLoss: Cox PH partial likelihood (Breslow, K causes) + CE, blended.
// Bucket-major pipeline, staged-coalesced pass A.

#define KC 4
#define NCLS 5
#define NB 8192              // duration buckets (durations ~ U[0,1))
#define CAPB 224             // slots per bucket (Poisson(122) + 9 sigma)
#define NPART 64             // scan partitions
#define BPP (NB / NPART)     // 128 buckets per partition
#define NMAX 1000000
#define TPB 256
#define EPS 1e-8
#define ALPHA 0.4

struct __align__(32) Elem {  // 32B = one sector
    float dur, f0, f1, f2, f3;
    float cause_bits;
    float pad0, pad1;
};

// ---- scratch (no allocations allowed) ----
__device__ Elem   g_elem[(size_t)NB * CAPB];   // bucket-major samples
__device__ Elem   g_ovf[4096];                 // overflow list (normally empty)
__device__ int    g_ovfb[4096];
__device__ int    g_cnt[NB];
__device__ int    g_ovf_cnt;
__device__ double g_bsum[NB * KC];
__device__ double g_sufx[NB * KC];
__device__ double g_part_sum[KC * NPART];
__device__ double g_part_sufx[KC * NPART];
__device__ double g_evsum[KC];
__device__ double g_evcnt[KC];
__device__ double g_ce;

// ---------------------------------------------------------------- helpers
__device__ __forceinline__ int bucket_of(float d) {
    int b = (int)(d * (float)NB);
    return b < 0 ? 0 : (b > NB - 1 ? NB - 1 : b);
}
__device__ __forceinline__ double warp_redd(double v) {
    #pragma unroll
    for (int o = 16; o; o >>= 1) v += __shfl_down_sync(0xffffffffu, v, o);
    return v;
}
__device__ __forceinline__ float elem_f(const float4& a, const float4& q, int c) {
    return (c == 0) ? a.y : (c == 1) ? a.z : (c == 2) ? a.w : q.x;
}

// ---------------------------------------------------------------- init
__global__ void k_init() {
    int i = blockIdx.x * blockDim.x + threadIdx.x;
    if (i < NB) g_cnt[i] = 0;
    if (i < KC * NPART) g_part_sum[i] = 0.0;
    if (i < KC) { g_evsum[i] = 0.0; g_evcnt[i] = 0.0; }
    if (i == 0) { g_ce = 0.0; g_ovf_cnt = 0; }
}

// ---------------------------------------------------------------- pass A (staged, fused scatter)
// Shared tile: union of log_h tile (256 samples x (8+1 pad) float4 = 36KB)
//              and logits tile (256 x (10+1 pad) float4 = 44KB).
__global__ void __launch_bounds__(TPB) k_passA(const float* __restrict__ log_h,
                        const float* __restrict__ logits,
                        const float* __restrict__ dur,
                        const int*   __restrict__ et,
                        const int*   __restrict__ labels,
                        int n, int M) {
    __shared__ float4 sh4[TPB * 11];
    __shared__ double s_ce;
    int t = threadIdx.x;
    if (t == 0) s_ce = 0.0;

    int blockBase = blockIdx.x * TPB;
    int cnt = n - blockBase; if (cnt > TPB) cnt = TPB;
    int i = blockBase + t;
    bool staged = (M == 8);

    float ex0 = 0.f, ex1 = 0.f, ex2 = 0.f, ex3 = 0.f;
    float inv = 1.0f / (float)M;

    // ---- stage log_h (coalesced) -> shared, then row-sum from shared ----
    if (staged) {
        int nf4 = cnt * 8;
        const float4* src = reinterpret_cast<const float4*>(log_h) + (size_t)blockBase * 8;
        for (int j = t; j < nf4; j += TPB) sh4[(j >> 3) * 9 + (j & 7)] = src[j];
    }
    __syncthreads();
    if (t < cnt) {
        float4 s = make_float4(0.f, 0.f, 0.f, 0.f);
        if (staged) {
            #pragma unroll
            for (int m = 0; m < 8; m++) {
                float4 v = sh4[t * 9 + m];
                s.x += v.x; s.y += v.y; s.z += v.z; s.w += v.w;
            }
        } else {
            const float4* lh = reinterpret_cast<const float4*>(log_h) + (size_t)i * M;
            for (int m = 0; m < M; m++) {
                float4 v = lh[m];
                s.x += v.x; s.y += v.y; s.z += v.z; s.w += v.w;
            }
        }
        ex0 = expf(fminf(fmaxf(s.x * inv, -50.f), 50.f));
        ex1 = expf(fminf(fmaxf(s.y * inv, -50.f), 50.f));
        ex2 = expf(fminf(fmaxf(s.z * inv, -50.f), 50.f));
        ex3 = expf(fminf(fmaxf(s.w * inv, -50.f), 50.f));

        float d = dur[i];
        int cause = et[i];
        int b = bucket_of(d);
        int pos = atomicAdd(&g_cnt[b], 1);
        if (pos < CAPB) {
            float4* p = reinterpret_cast<float4*>(&g_elem[(size_t)b * CAPB + pos]);
            p[0] = make_float4(d, ex0, ex1, ex2);
            p[1] = make_float4(ex3, __int_as_float(cause), 0.f, 0.f);
        } else {
            int oi = atomicAdd(&g_ovf_cnt, 1);
            float4* p = reinterpret_cast<float4*>(&g_ovf[oi]);
            p[0] = make_float4(d, ex0, ex1, ex2);
            p[1] = make_float4(ex3, __int_as_float(cause), 0.f, 0.f);
            g_ovfb[oi] = b;
        }
    }
    __syncthreads();

    // ---- stage logits (coalesced) -> shared, then CE from shared ----
    if (staged) {
        int nf4 = cnt * 10;
        const float4* src = reinterpret_cast<const float4*>(logits) + (size_t)blockBase * 10;
        for (int j = t; j < nf4; j += TPB) {
            int l = j / 10, r = j - l * 10;
            sh4[l * 11 + r] = src[j];
        }
    }
    __syncthreads();

    double ce = 0.0;
    if (t < cnt) {
        float lm[NCLS];
        #pragma unroll
        for (int j = 0; j < NCLS; j++) lm[j] = 0.f;
        if (staged) {
            #pragma unroll
            for (int j = 0; j < 10; j++) {
                float4 v = sh4[t * 11 + j];
                int base = j * 4;
                lm[(base + 0) % NCLS] += v.x;
                lm[(base + 1) % NCLS] += v.y;
                lm[(base + 2) % NCLS] += v.z;
                lm[(base + 3) % NCLS] += v.w;
            }
        } else {
            const float* lg = logits + (size_t)i * M * NCLS;
            for (int q = 0; q < M * NCLS; q++) lm[q % NCLS] += lg[q];
        }
        float mj[NCLS], mx = -3.4e38f;
        #pragma unroll
        for (int j = 0; j < NCLS; j++) { mj[j] = lm[j] * inv; mx = fmaxf(mx, mj[j]); }
        float se = 0.f;
        #pragma unroll
        for (int j = 0; j < NCLS; j++) se += expf(mj[j] - mx);
        ce = (double)(mx + logf(se) - mj[labels[i]]);
    }
    double v = warp_redd(ce);
    if ((t & 31) == 0 && v != 0.0) atomicAdd(&s_ce, v);
    __syncthreads();
    if (t == 0 && s_ce != 0.0) atomicAdd(&g_ce, s_ce);
}

// ---------------------------------------------------------------- bucket sums (+overflow, +part sums)
__global__ void __launch_bounds__(128) k_bsum() {
    __shared__ double sw[KC][4];
    int b = blockIdx.x, t = threadIdx.x;
    int w = t >> 5, lane = t & 31;
    int m = min(g_cnt[b], CAPB);
    double a0 = 0, a1 = 0, a2 = 0, a3 = 0;
    for (int j = t; j < m; j += 128) {
        const float4* p = reinterpret_cast<const float4*>(&g_elem[(size_t)b * CAPB + j]);
        float4 a = p[0], q = p[1];
        a0 += a.y; a1 += a.z; a2 += a.w; a3 += q.x;
    }
    a0 = warp_redd(a0); a1 = warp_redd(a1); a2 = warp_redd(a2); a3 = warp_redd(a3);
    if (lane == 0) { sw[0][w] = a0; sw[1][w] = a1; sw[2][w] = a2; sw[3][w] = a3; }
    __syncthreads();
    if (t < KC) {
        double s = sw[t][0] + sw[t][1] + sw[t][2] + sw[t][3];
        int nov = g_ovf_cnt;                 // normally 0
        for (int j = 0; j < nov; j++) {
            if (g_ovfb[j] == b) {
                const float4* p = reinterpret_cast<const float4*>(&g_ovf[j]);
                float4 a = p[0], q = p[1];
                s += (double)elem_f(a, q, t);
            }
        }
        g_bsum[b * KC + t] = s;
        atomicAdd(&g_part_sum[t * NPART + b / BPP], s);
    }
}

// ---------------------------------------------------------------- suffix over parts (1 block)
__global__ void __launch_bounds__(NPART) k_sufB() {
    __shared__ double sd[NPART];
    int t = threadIdx.x;
    for (int c = 0; c < KC; c++) {
        double own = g_part_sum[c * NPART + t];
        sd[t] = own;
        __syncthreads();
        for (int off = 1; off < NPART; off <<= 1) {
            double v = (t + off < NPART) ? sd[t + off] : 0.0;
            __syncthreads();
            sd[t] += v;
            __syncthreads();
        }
        g_part_sufx[c * NPART + t] = sd[t] - own;  // exclusive suffix over parts
        __syncthreads();
    }
}

// ---------------------------------------------------------------- within-part suffix fixup
__global__ void __launch_bounds__(BPP) k_sufC() {
    __shared__ double sd[BPP];
    int t = threadIdx.x, p = blockIdx.x;
    int b = p * BPP + t;
    for (int c = 0; c < KC; c++) {
        double own = g_bsum[b * KC + c];
        sd[t] = own;
        __syncthreads();
        for (int off = 1; off < BPP; off <<= 1) {
            double v = (t + off < BPP) ? sd[t + off] : 0.0;
            __syncthreads();
            sd[t] += v;
            __syncthreads();
        }
        g_sufx[b * KC + c] = g_part_sufx[c * NPART + p] + sd[t] - own;
        __syncthreads();
    }
}

// ---------------------------------------------------------------- events: block-per-bucket
__global__ void __launch_bounds__(128) k_events() {
    __shared__ float  sh_dur[CAPB];
    __shared__ float  sh_f[KC][CAPB];
    __shared__ int    sh_c[CAPB];
    __shared__ double s_sum[KC];
    __shared__ double s_cnt[KC];

    int b = blockIdx.x, t = threadIdx.x;
    if (t < KC) { s_sum[t] = 0.0; s_cnt[t] = 0.0; }

    int cnt = g_cnt[b];
    int m = min(cnt, CAPB);
    if (m == 0) return;

    for (int j = t; j < m; j += 128) {
        const float4* p = reinterpret_cast<const float4*>(&g_elem[(size_t)b * CAPB + j]);
        float4 a = p[0], q = p[1];
        sh_dur[j]  = a.x;
        sh_f[0][j] = a.y;
        sh_f[1][j] = a.z;
        sh_f[2][j] = a.w;
        sh_f[3][j] = q.x;
        sh_c[j]    = __float_as_int(q.y);
    }
    __syncthreads();

    int nov = (cnt > CAPB) ? g_ovf_cnt : 0;

    for (int j = t; j < m; j += 128) {
        int cv = sh_c[j];
        if (cv > 0) {
            int cc = cv - 1;
            float d_e = sh_dur[j];
            float fown = sh_f[cc][j];
            const float* fp = sh_f[cc];
            float acc = 0.f;
            for (int j2 = 0; j2 < m; j2++)
                acc += (sh_dur[j2] >= d_e) ? fp[j2] : 0.f;
            for (int j2 = 0; j2 < nov; j2++) {
                if (g_ovfb[j2] == b) {
                    const float4* p = reinterpret_cast<const float4*>(&g_ovf[j2]);
                    float4 a = p[0], q = p[1];
                    acc += (a.x >= d_e) ? elem_f(a, q, cc) : 0.f;
                }
            }
            double denom = g_sufx[b * KC + cc] + (double)acc;
            atomicAdd(&s_sum[cc], (double)logf(fown) - log(denom + EPS));
            atomicAdd(&s_cnt[cc], 1.0);
        }
    }
    __syncthreads();
    if (t < KC && s_cnt[t] != 0.0) {
        atomicAdd(&g_evsum[t], s_sum[t]);
        atomicAdd(&g_evcnt[t], s_cnt[t]);
    }
}

// ---------------------------------------------------------------- finalize (+ overflow events)
__global__ void k_fin(float* __restrict__ out, int n) {
    double esum[KC], ecnt[KC];
    #pragma unroll
    for (int c = 0; c < KC; c++) { esum[c] = g_evsum[c]; ecnt[c] = g_evcnt[c]; }

    int nov = g_ovf_cnt;  // normally 0
    for (int i = 0; i < nov; i++) {
        const float4* p = reinterpret_cast<const float4*>(&g_ovf[i]);
        float4 a = p[0], q = p[1];
        int cv = __float_as_int(q.y);
        if (cv <= 0) continue;
        int cc = cv - 1, b = g_ovfb[i];
        float d_e = a.x;
        float acc = 0.f;
        int m = min(g_cnt[b], CAPB);
        for (int j = 0; j < m; j++) {
            const float4* pj = reinterpret_cast<const float4*>(&g_elem[(size_t)b * CAPB + j]);
            float4 aj = pj[0], qj = pj[1];
            acc += (aj.x >= d_e) ? elem_f(aj, qj, cc) : 0.f;
        }
        for (int j = 0; j < nov; j++) {
            if (g_ovfb[j] == b) {
                const float4* pj = reinterpret_cast<const float4*>(&g_ovf[j]);
                float4 aj = pj[0], qj = pj[1];
                acc += (aj.x >= d_e) ? elem_f(aj, qj, cc) : 0.f;
            }
        }
        double denom = g_sufx[b * KC + cc] + (double)acc;
        esum[cc] += (double)logf(elem_f(a, q, cc)) - log(denom + EPS);
        ecnt[cc] += 1.0;
    }

    double ls = 0.0;
    #pragma unroll
    for (int c = 0; c < KC; c++) ls += -esum[c] / (ecnt[c] + EPS);
    double lc = g_ce / (double)n;
    out[0] = (float)(ALPHA * ls + (1.0 - ALPHA) * lc);
}

// ---------------------------------------------------------------- launch
extern "C" void kernel_launch(void* const* d_in, const int* in_sizes, int n_in,
                              void* d_out, int out_size) {
    const float* log_h  = (const float*)d_in[0];
    const float* logits = (const float*)d_in[1];
    const float* dur    = (const float*)d_in[2];
    const int*   et     = (const int*)d_in[3];
    const int*   labels = (const int*)d_in[4];
    float* out = (float*)d_out;

    int n = in_sizes[2];
    int M = in_sizes[0] / (n * KC);

    int nb = (n + TPB - 1) / TPB;

    k_init<<<(NB + TPB - 1) / TPB, TPB>>>();
    k_passA<<<nb, TPB>>>(log_h, logits, dur, et, labels, n, M);
    k_bsum<<<NB, 128>>>();
    k_sufB<<<1, NPART>>>();
    k_sufC<<<NPART, BPP>>>();
    k_events<<<NB, 128>>>();
    k_fin<<<1, 1>>>(out, n);
}